// round 6
// baseline (speedup 1.0000x reference)
#include <cuda_runtime.h>
#include <math.h>

#define Vn 10000
#define Dn 300
#define Bn 64
#define Ln 128
#define CFc 5.0f
#define EPSc 1e-8f
#define NF4 2500   // Vn/4

// ------- scratch (device globals; no allocation allowed) -------
__device__ float g_per[Bn * Dn];
__device__ float g_ctx[Dn];
__device__ float g_cn;
__device__ float g_A[Vn];
__device__ float g_Bc[Vn];
__device__ int   g_flag[Vn];
__device__ float g_invZ[Vn];
__device__ float g_PtA[(size_t)Bn * Vn];  // partial P, tokens [0,64)
__device__ float g_PtB[(size_t)Bn * Vn];  // partial P, tokens [64,128)

// ------- K0: zero flags + output -------
__global__ void k_zero(float* __restrict__ out) {
    int i = blockIdx.x * blockDim.x + threadIdx.x;
    if (i < Vn) g_flag[i] = 0;
    if (i < Bn * Dn) out[i] = 0.0f;
}

// ------- K1: per-sample ragged mean of embed rows (token-parallel) -------
__global__ void k_context(const int* __restrict__ list,
                          const int* __restrict__ lens,
                          const float* __restrict__ embed) {
    __shared__ float4 sacc[4][80];
    int b = blockIdx.x;
    int len = lens[b];
    int t = threadIdx.x;
    int comp = t & 127;
    int grp = t >> 7;
    float4 acc = make_float4(0.f, 0.f, 0.f, 0.f);
    if (comp < 75) {
        for (int l = grp; l < len; l += 4) {
            const float4* row = (const float4*)(embed + (size_t)list[b * Ln + l] * Dn);
            float4 x = row[comp];
            acc.x += x.x; acc.y += x.y; acc.z += x.z; acc.w += x.w;
        }
        sacc[grp][comp] = acc;
    }
    __syncthreads();
    if (grp == 0 && comp < 75) {
        float4 s = sacc[0][comp];
#pragma unroll
        for (int g = 1; g < 4; g++) {
            float4 x = sacc[g][comp];
            s.x += x.x; s.y += x.y; s.z += x.z; s.w += x.w;
        }
        float inv = 1.0f / (float)(len > 0 ? len : 1);
        s.x *= inv; s.y *= inv; s.z *= inv; s.w *= inv;
        ((float4*)(g_per + (size_t)b * Dn))[comp] = s;
    }
}

// ------- K2: reduce over batch -> context + norm -------
__global__ void k_reduce_ctx() {
    __shared__ float sred[512];
    int d = threadIdx.x;
    float c = 0.f;
    if (d < Dn) {
        float s = 0.f;
        for (int b = 0; b < Bn; b++) s += g_per[b * Dn + d];
        c = s * (1.0f / (float)Bn);
        g_ctx[d] = c;
    }
    sred[d] = c * c;
    __syncthreads();
    for (int s = 256; s > 0; s >>= 1) {
        if (d < s) sred[d] += sred[d + s];
        __syncthreads();
    }
    if (d == 0) g_cn = sqrtf(sred[0]);
}

// ------- K3: cos-sim -> A[v], B[v]. 2 rows per warp for MLP. -------
__global__ void k_ab(const float* __restrict__ cw,
                     const float* __restrict__ aff,
                     const float* __restrict__ lam) {
    __shared__ float4 sctx[75];
    for (int i = threadIdx.x; i < 75; i += 256)
        sctx[i] = ((const float4*)g_ctx)[i];
    __syncthreads();
    int w = threadIdx.x >> 5, lane = threadIdx.x & 31;
    int v0 = (blockIdx.x * 8 + w) * 2;
    if (v0 >= Vn) return;
    const float4* r0 = (const float4*)(cw + (size_t)v0 * Dn);
    const float4* r1 = (const float4*)(cw + (size_t)(v0 + 1) * Dn);
    float d0 = 0.f, n0 = 0.f, d1 = 0.f, n1 = 0.f;
#pragma unroll
    for (int i = 0; i < 3; i++) {
        int idx = lane + i * 32;
        if (idx < 75) {
            float4 x = r0[idx];
            float4 y = r1[idx];
            float4 c = sctx[idx];
            d0 += x.x * c.x + x.y * c.y + x.z * c.z + x.w * c.w;
            n0 += x.x * x.x + x.y * x.y + x.z * x.z + x.w * x.w;
            d1 += y.x * c.x + y.y * c.y + y.z * c.z + y.w * c.w;
            n1 += y.x * y.x + y.y * y.y + y.z * y.z + y.w * y.w;
        }
    }
#pragma unroll
    for (int o = 16; o > 0; o >>= 1) {
        d0 += __shfl_xor_sync(0xffffffffu, d0, o);
        n0 += __shfl_xor_sync(0xffffffffu, n0, o);
        d1 += __shfl_xor_sync(0xffffffffu, d1, o);
        n1 += __shfl_xor_sync(0xffffffffu, n1, o);
    }
    if (lane == 0) {
        float cn = g_cn;
        float c0 = fabsf(d0) / fmaxf(cn * sqrtf(n0), EPSc);
        float c1 = fabsf(d1) / fmaxf(cn * sqrtf(n1), EPSc);
        float la0 = lam[v0], la1 = lam[v0 + 1];
        g_A[v0]      = CFc * la0 * c0;
        g_Bc[v0]     = CFc * (1.0f - la0) * aff[v0];
        g_A[v0 + 1]  = CFc * la1 * c1;
        g_Bc[v0 + 1] = CFc * (1.0f - la1) * aff[v0 + 1];
    }
}

// ------- K4: flag used concepts -------
__global__ void k_flag(const int* __restrict__ list,
                       const int* __restrict__ lens) {
    int i = blockIdx.x * blockDim.x + threadIdx.x;
    if (i >= Bn * Ln) return;
    int b = i / Ln, l = i % Ln;
    if (l < lens[b]) g_flag[list[i]] = 1;
}

// ------- K5: softmax denominators, 4-wide strip batching -------
__global__ void k_z(const float* __restrict__ edge) {
    int c = blockIdx.x;
    if (!g_flag[c]) return;
    const float4* row = (const float4*)(edge + (size_t)c * Vn);
    const float4* A4 = (const float4*)g_A;
    const float4* B4 = (const float4*)g_Bc;
    int t = threadIdx.x;  // 256
    float s = 0.f;
    float4 z4 = make_float4(0.f, 0.f, 0.f, 0.f);
    for (int base = t; base < NF4; base += 1024) {
        int i1 = base + 256, i2 = base + 512, i3 = base + 768;
        float4 e0 = row[base], a0 = A4[base], b0 = B4[base];
        float4 e1 = (i1 < NF4) ? row[i1] : z4;
        float4 a1 = (i1 < NF4) ? A4[i1] : z4;
        float4 b1 = (i1 < NF4) ? B4[i1] : z4;
        float4 e2 = (i2 < NF4) ? row[i2] : z4;
        float4 a2 = (i2 < NF4) ? A4[i2] : z4;
        float4 b2 = (i2 < NF4) ? B4[i2] : z4;
        float4 e3 = (i3 < NF4) ? row[i3] : z4;
        float4 a3 = (i3 < NF4) ? A4[i3] : z4;
        float4 b3 = (i3 < NF4) ? B4[i3] : z4;
        s += __expf(e0.x * a0.x + (e0.x > 0.f ? b0.x : 0.f));
        s += __expf(e0.y * a0.y + (e0.y > 0.f ? b0.y : 0.f));
        s += __expf(e0.z * a0.z + (e0.z > 0.f ? b0.z : 0.f));
        s += __expf(e0.w * a0.w + (e0.w > 0.f ? b0.w : 0.f));
        if (i1 < NF4) {
            s += __expf(e1.x * a1.x + (e1.x > 0.f ? b1.x : 0.f));
            s += __expf(e1.y * a1.y + (e1.y > 0.f ? b1.y : 0.f));
            s += __expf(e1.z * a1.z + (e1.z > 0.f ? b1.z : 0.f));
            s += __expf(e1.w * a1.w + (e1.w > 0.f ? b1.w : 0.f));
        }
        if (i2 < NF4) {
            s += __expf(e2.x * a2.x + (e2.x > 0.f ? b2.x : 0.f));
            s += __expf(e2.y * a2.y + (e2.y > 0.f ? b2.y : 0.f));
            s += __expf(e2.z * a2.z + (e2.z > 0.f ? b2.z : 0.f));
            s += __expf(e2.w * a2.w + (e2.w > 0.f ? b2.w : 0.f));
        }
        if (i3 < NF4) {
            s += __expf(e3.x * a3.x + (e3.x > 0.f ? b3.x : 0.f));
            s += __expf(e3.y * a3.y + (e3.y > 0.f ? b3.y : 0.f));
            s += __expf(e3.z * a3.z + (e3.z > 0.f ? b3.z : 0.f));
            s += __expf(e3.w * a3.w + (e3.w > 0.f ? b3.w : 0.f));
        }
    }
#pragma unroll
    for (int o = 16; o > 0; o >>= 1) s += __shfl_xor_sync(0xffffffffu, s, o);
    __shared__ float sr[8];
    if ((t & 31) == 0) sr[t >> 5] = s;
    __syncthreads();
    if (t < 8) {
        float x = sr[t];
#pragma unroll
        for (int o = 4; o > 0; o >>= 1) x += __shfl_xor_sync(0xffu, x, o);
        if (t == 0) g_invZ[c] = 1.0f / x;
    }
}

// ------- K6: partial P. grid (20, 64, 2): z halves the token range. -------
#define VC 512
__global__ void k_p(const int* __restrict__ list,
                    const int* __restrict__ lens,
                    const float* __restrict__ edge) {
    __shared__ int   sc[64];
    __shared__ float siz[64];
    int b = blockIdx.y;
    int half = blockIdx.z;
    int v0 = blockIdx.x * VC;
    int t = threadIdx.x;  // 128
    int len = lens[b];
    float* outb = half ? g_PtB : g_PtA;
    bool act = (v0 + t * 4) < Vn;
    int f4 = v0 / 4 + t;

    int l0 = half * 64;
    int myn = min(len - l0, 64);
    if (myn <= 0) {
        if (act) ((float4*)(outb + (size_t)b * Vn))[f4] =
            make_float4(0.f, 0.f, 0.f, 0.f);
        return;
    }
    if (t < myn) {
        int c = list[b * Ln + l0 + t];
        sc[t] = c;
        siz[t] = g_invZ[c];
    }
    __syncthreads();

    float4 a4 = make_float4(0.f, 0.f, 0.f, 0.f), b4 = a4;
    if (act) {
        a4 = ((const float4*)g_A)[f4];
        b4 = ((const float4*)g_Bc)[f4];
    }
    float4 acc = make_float4(0.f, 0.f, 0.f, 0.f);
    const float4* e4 = (const float4*)edge;
    float4 z4 = make_float4(0.f, 0.f, 0.f, 0.f);

    int l = 0;
    for (; l + 4 <= myn; l += 4) {
        float4 e0 = act ? e4[(size_t)sc[l]     * NF4 + f4] : z4;
        float4 e1 = act ? e4[(size_t)sc[l + 1] * NF4 + f4] : z4;
        float4 e2 = act ? e4[(size_t)sc[l + 2] * NF4 + f4] : z4;
        float4 e3 = act ? e4[(size_t)sc[l + 3] * NF4 + f4] : z4;
        float z0 = siz[l], z1 = siz[l + 1], z2 = siz[l + 2], z3 = siz[l + 3];
        acc.x += __expf(e0.x * a4.x + (e0.x > 0.f ? b4.x : 0.f)) * z0;
        acc.y += __expf(e0.y * a4.y + (e0.y > 0.f ? b4.y : 0.f)) * z0;
        acc.z += __expf(e0.z * a4.z + (e0.z > 0.f ? b4.z : 0.f)) * z0;
        acc.w += __expf(e0.w * a4.w + (e0.w > 0.f ? b4.w : 0.f)) * z0;
        acc.x += __expf(e1.x * a4.x + (e1.x > 0.f ? b4.x : 0.f)) * z1;
        acc.y += __expf(e1.y * a4.y + (e1.y > 0.f ? b4.y : 0.f)) * z1;
        acc.z += __expf(e1.z * a4.z + (e1.z > 0.f ? b4.z : 0.f)) * z1;
        acc.w += __expf(e1.w * a4.w + (e1.w > 0.f ? b4.w : 0.f)) * z1;
        acc.x += __expf(e2.x * a4.x + (e2.x > 0.f ? b4.x : 0.f)) * z2;
        acc.y += __expf(e2.y * a4.y + (e2.y > 0.f ? b4.y : 0.f)) * z2;
        acc.z += __expf(e2.z * a4.z + (e2.z > 0.f ? b4.z : 0.f)) * z2;
        acc.w += __expf(e2.w * a4.w + (e2.w > 0.f ? b4.w : 0.f)) * z2;
        acc.x += __expf(e3.x * a4.x + (e3.x > 0.f ? b4.x : 0.f)) * z3;
        acc.y += __expf(e3.y * a4.y + (e3.y > 0.f ? b4.y : 0.f)) * z3;
        acc.z += __expf(e3.z * a4.z + (e3.z > 0.f ? b4.z : 0.f)) * z3;
        acc.w += __expf(e3.w * a4.w + (e3.w > 0.f ? b4.w : 0.f)) * z3;
    }
    for (; l < myn; l++) {
        float4 e0 = act ? e4[(size_t)sc[l] * NF4 + f4] : z4;
        float z0 = siz[l];
        acc.x += __expf(e0.x * a4.x + (e0.x > 0.f ? b4.x : 0.f)) * z0;
        acc.y += __expf(e0.y * a4.y + (e0.y > 0.f ? b4.y : 0.f)) * z0;
        acc.z += __expf(e0.z * a4.z + (e0.z > 0.f ? b4.z : 0.f)) * z0;
        acc.w += __expf(e0.w * a4.w + (e0.w > 0.f ? b4.w : 0.f)) * z0;
    }
    float invd = 1.0f / (float)(len > 0 ? len : 1);
    acc.x *= invd; acc.y *= invd; acc.z *= invd; acc.w *= invd;
    if (act) ((float4*)(outb + (size_t)b * Vn))[f4] = acc;
}

// ------- K7: out = (PA+PB) @ W, K-split + atomics -------
#define KT 32
#define DT 32
#define KSPLIT 16
#define KCHUNK 625
__global__ void k_out(const float* __restrict__ cw, float* __restrict__ out) {
    int d0 = blockIdx.x * DT;
    int kbeg = blockIdx.y * KCHUNK;
    int kend = min(kbeg + KCHUNK, Vn);
    __shared__ float sP[KT][Bn + 4];
    __shared__ float sW[KT][DT + 4];
    int t = threadIdx.x;
    int tb = t & 15;
    int td = t >> 4;
    float acc[4][4];
#pragma unroll
    for (int i = 0; i < 4; i++)
#pragma unroll
        for (int j = 0; j < 4; j++) acc[i][j] = 0.f;

    for (int k0 = kbeg; k0 < kend; k0 += KT) {
        for (int i = t; i < KT * Bn; i += 128) {
            int b = i >> 5, kk = i & 31;
            int kv = k0 + kk;
            sP[kk][b] = (kv < kend)
                ? g_PtA[(size_t)b * Vn + kv] + g_PtB[(size_t)b * Vn + kv] : 0.f;
        }
        for (int i = t; i < KT * DT; i += 128) {
            int kk = i / DT, j = i % DT;
            int kv = k0 + kk, d = d0 + j;
            sW[kk][j] = (kv < kend && d < Dn) ? cw[(size_t)kv * Dn + d] : 0.f;
        }
        __syncthreads();
#pragma unroll 8
        for (int k = 0; k < KT; k++) {
            float p0 = sP[k][tb * 4], p1 = sP[k][tb * 4 + 1];
            float p2 = sP[k][tb * 4 + 2], p3 = sP[k][tb * 4 + 3];
            float w0 = sW[k][td * 4], w1 = sW[k][td * 4 + 1];
            float w2 = sW[k][td * 4 + 2], w3 = sW[k][td * 4 + 3];
            acc[0][0] += p0 * w0; acc[0][1] += p0 * w1; acc[0][2] += p0 * w2; acc[0][3] += p0 * w3;
            acc[1][0] += p1 * w0; acc[1][1] += p1 * w1; acc[1][2] += p1 * w2; acc[1][3] += p1 * w3;
            acc[2][0] += p2 * w0; acc[2][1] += p2 * w1; acc[2][2] += p2 * w2; acc[2][3] += p2 * w3;
            acc[3][0] += p3 * w0; acc[3][1] += p3 * w1; acc[3][2] += p3 * w2; acc[3][3] += p3 * w3;
        }
        __syncthreads();
    }
#pragma unroll
    for (int i = 0; i < 4; i++) {
        int b = tb * 4 + i;
#pragma unroll
        for (int j = 0; j < 4; j++) {
            int d = d0 + td * 4 + j;
            if (d < Dn) atomicAdd(&out[b * Dn + d], acc[i][j]);
        }
    }
}

extern "C" void kernel_launch(void* const* d_in, const int* in_sizes, int n_in,
                              void* d_out, int out_size) {
    const int*   list  = (const int*)d_in[0];
    const int*   lens  = (const int*)d_in[1];
    const float* embed = (const float*)d_in[2];
    const float* cw    = (const float*)d_in[3];
    const float* edge  = (const float*)d_in[4];
    const float* aff   = (const float*)d_in[5];
    const float* lam   = (const float*)d_in[6];
    float* out = (float*)d_out;

    k_zero<<<75, 256>>>(out);
    k_context<<<Bn, 512>>>(list, lens, embed);
    k_reduce_ctx<<<1, 512>>>();
    k_ab<<<625, 256>>>(cw, aff, lam);
    k_flag<<<(Bn * Ln + 255) / 256, 256>>>(list, lens);
    k_z<<<Vn, 256>>>(edge);
    k_p<<<dim3((Vn + VC - 1) / VC, Bn, 2), 128>>>(list, lens, edge);
    k_out<<<dim3((Dn + DT - 1) / DT, KSPLIT), 128>>>(cw, out);
}